// round 1
// baseline (speedup 1.0000x reference)
#include <cuda_runtime.h>
#include <math.h>

#define N_MAX 50000
#define E_MAX 800000
#define F_IN  512
#define NHEAD 8
#define HC    256
#define CLS   40

// ------------------- scratch (static device globals; no allocs) -------------
__device__ float g_h1[N_MAX * HC];      // layer-1 features per head (pre-attn)
__device__ float g_feat2[N_MAX * HC];   // elu(aggregated + b1) = layer-2 input
__device__ float g_h2[N_MAX * CLS];     // layer-2 transformed features
__device__ float g_as1[N_MAX * NHEAD];
__device__ float g_ad1[N_MAX * NHEAD];
__device__ float g_as2[N_MAX];
__device__ float g_ad2[N_MAX];
__device__ int   g_deg[N_MAX];
__device__ int   g_rowptr[N_MAX + 1];
__device__ int   g_cursor[N_MAX];
__device__ int   g_col[E_MAX + N_MAX];

// ------------------------------- CSR build ---------------------------------
__global__ void k_zero_deg(int n) {
    int i = blockIdx.x * blockDim.x + threadIdx.x;
    if (i < n) g_deg[i] = 0;
}

__global__ void k_count(const int* __restrict__ ei, int e, int n) {
    int i = blockIdx.x * blockDim.x + threadIdx.x;
    int tot = e + n;
    if (i >= tot) return;
    int dst = (i < e) ? ei[e + i] : (i - e);
    atomicAdd(&g_deg[dst], 1);
}

// single-block scan: rowptr (exclusive on [0..n]) + cursor copy
__global__ void k_scan(int n) {
    __shared__ int wsum[32];
    int t = threadIdx.x, lane = t & 31, w = t >> 5;
    int carry = 0;
    for (int base = 0; base < n; base += 1024) {
        int i = base + t;
        int v = (i < n) ? g_deg[i] : 0;
        int xv = v;
#pragma unroll
        for (int off = 1; off < 32; off <<= 1) {
            int u = __shfl_up_sync(0xffffffffu, xv, off);
            if (lane >= off) xv += u;
        }
        if (lane == 31) wsum[w] = xv;
        __syncthreads();
        if (w == 0) {
            int y = wsum[lane];
#pragma unroll
            for (int off = 1; off < 32; off <<= 1) {
                int u = __shfl_up_sync(0xffffffffu, y, off);
                if (lane >= off) y += u;
            }
            wsum[lane] = y;
        }
        __syncthreads();
        int prev = (w > 0) ? wsum[w - 1] : 0;
        int incl = xv + prev;
        int tot = wsum[31];
        if (i < n) {
            g_rowptr[i + 1] = carry + incl;
            g_cursor[i] = carry + incl - v;
        }
        carry += tot;
        __syncthreads();
    }
    if (t == 0) g_rowptr[0] = 0;
}

__global__ void k_scatter(const int* __restrict__ ei, int e, int n) {
    int i = blockIdx.x * blockDim.x + threadIdx.x;
    int tot = e + n;
    if (i >= tot) return;
    int src = (i < e) ? ei[i] : (i - e);
    int dst = (i < e) ? ei[e + i] : (i - e);
    int p = atomicAdd(&g_cursor[dst], 1);
    g_col[p] = src;
}

// ------------------- GEMM1: h1 = x @ W1  (M=n, K=512, N=256) ----------------
__global__ void __launch_bounds__(256) k_gemm1(const float* __restrict__ x,
                                               const float* __restrict__ W, int n) {
    __shared__ float As[8][128];
    __shared__ float Bs[8][128];
    int t = threadIdx.x;
    int rowbase = blockIdx.y * 128;
    int colbase = blockIdx.x * 128;
    int lr = t >> 1, lh = t & 1;           // A loader: row, k-quad half
    int lk = t >> 5, lc = (t & 31) << 2;   // B loader: k-row, col quad
    int ty = t >> 4, tx = t & 15;

    float acc[8][8];
#pragma unroll
    for (int i = 0; i < 8; i++)
#pragma unroll
        for (int j = 0; j < 8; j++) acc[i][j] = 0.f;

    for (int k0 = 0; k0 < F_IN; k0 += 8) {
        float4 av = make_float4(0.f, 0.f, 0.f, 0.f);
        int gr = rowbase + lr;
        if (gr < n) av = *(const float4*)&x[gr * F_IN + k0 + lh * 4];
        As[lh * 4 + 0][lr] = av.x;
        As[lh * 4 + 1][lr] = av.y;
        As[lh * 4 + 2][lr] = av.z;
        As[lh * 4 + 3][lr] = av.w;
        float4 bv = *(const float4*)&W[(k0 + lk) * HC + colbase + lc];
        *(float4*)&Bs[lk][lc] = bv;
        __syncthreads();
#pragma unroll
        for (int kk = 0; kk < 8; kk++) {
            float4 a0 = *(const float4*)&As[kk][ty * 8];
            float4 a1 = *(const float4*)&As[kk][ty * 8 + 4];
            float4 b0 = *(const float4*)&Bs[kk][tx * 8];
            float4 b1 = *(const float4*)&Bs[kk][tx * 8 + 4];
            float a[8] = {a0.x, a0.y, a0.z, a0.w, a1.x, a1.y, a1.z, a1.w};
            float b[8] = {b0.x, b0.y, b0.z, b0.w, b1.x, b1.y, b1.z, b1.w};
#pragma unroll
            for (int i = 0; i < 8; i++)
#pragma unroll
                for (int j = 0; j < 8; j++) acc[i][j] += a[i] * b[j];
        }
        __syncthreads();
    }
#pragma unroll
    for (int i = 0; i < 8; i++) {
        int gr = rowbase + ty * 8 + i;
        if (gr < n) {
            *(float4*)&g_h1[gr * HC + colbase + tx * 8] =
                make_float4(acc[i][0], acc[i][1], acc[i][2], acc[i][3]);
            *(float4*)&g_h1[gr * HC + colbase + tx * 8 + 4] =
                make_float4(acc[i][4], acc[i][5], acc[i][6], acc[i][7]);
        }
    }
}

// --------------- per-node attention dot products, layer 1 -------------------
__global__ void k_alpha1(const float* __restrict__ aw_s,
                         const float* __restrict__ aw_d, int n) {
    int warp = (blockIdx.x * blockDim.x + threadIdx.x) >> 5;
    int lane = threadIdx.x & 31;
    if (warp >= n) return;
    const float* hrow = &g_h1[warp * HC];
    float rs[8], rd[8];
#pragma unroll
    for (int i = 0; i < 8; i++) {
        float v = hrow[i * 32 + lane];
        float s = v * aw_s[i * 32 + lane];
        float d = v * aw_d[i * 32 + lane];
#pragma unroll
        for (int off = 16; off >= 1; off >>= 1) {
            s += __shfl_xor_sync(0xffffffffu, s, off);
            d += __shfl_xor_sync(0xffffffffu, d, off);
        }
        rs[i] = s; rd[i] = d;
    }
    if (lane == 0) {
#pragma unroll
        for (int i = 0; i < 8; i++) {
            g_as1[warp * 8 + i] = rs[i];
            g_ad1[warp * 8 + i] = rd[i];
        }
    }
}

// ---------- fused segment-softmax + aggregation + bias + ELU (layer 1) ------
__global__ void __launch_bounds__(256) k_gat1(const float* __restrict__ b1, int n) {
    const int CH = 64;
    int node = blockIdx.x;
    int tid = threadIdx.x;
    int base = g_rowptr[node];
    int deg = g_rowptr[node + 1] - base;

    __shared__ float red[256];
    __shared__ float hmax[8], hden[8], adl[8];
    __shared__ float sal[CH * 8];
    __shared__ int ssrc[CH];

    if (tid < 8) adl[tid] = g_ad1[node * 8 + tid];
    __syncthreads();
    int hh = tid & 7;
    float ad = adl[hh];

    // pass A: per-head max
    float pm = -1e30f;
    for (int i = tid; i < deg * 8; i += 256) {
        int j = i >> 3;
        int s = g_col[base + j];
        float e = g_as1[s * 8 + hh] + ad;
        e = e > 0.f ? e : 0.2f * e;
        pm = fmaxf(pm, e);
    }
    red[tid] = pm;
    __syncthreads();
#pragma unroll
    for (int st = 128; st >= 8; st >>= 1) {
        if (tid < st) red[tid] = fmaxf(red[tid], red[tid + st]);
        __syncthreads();
    }
    if (tid < 8) hmax[tid] = red[tid];
    __syncthreads();
    float mh = hmax[hh];

    // pass B: per-head denominator
    float ps = 0.f;
    for (int i = tid; i < deg * 8; i += 256) {
        int j = i >> 3;
        int s = g_col[base + j];
        float e = g_as1[s * 8 + hh] + ad;
        e = e > 0.f ? e : 0.2f * e;
        ps += __expf(e - mh);
    }
    red[tid] = ps;
    __syncthreads();
#pragma unroll
    for (int st = 128; st >= 8; st >>= 1) {
        if (tid < st) red[tid] += red[tid + st];
        __syncthreads();
    }
    if (tid < 8) hden[tid] = red[tid] + 1e-16f;
    __syncthreads();
    float dh = hden[hh];

    // pass C: aggregate; thread tid owns slot (h = tid/32, c = tid%32)
    float acc = 0.f;
    int myh = tid >> 5;
    for (int cb = 0; cb < deg; cb += CH) {
        int m = min(CH, deg - cb);
        __syncthreads();
        if (tid < m) ssrc[tid] = g_col[base + cb + tid];
        __syncthreads();
        for (int i = tid; i < m * 8; i += 256) {
            int j = i >> 3;
            float e = g_as1[ssrc[j] * 8 + hh] + ad;
            e = e > 0.f ? e : 0.2f * e;
            sal[i] = __expf(e - mh) / dh;
        }
        __syncthreads();
        for (int j = 0; j < m; j++) {
            acc += sal[j * 8 + myh] * g_h1[ssrc[j] * HC + tid];
        }
    }
    float v = acc + b1[tid];
    g_feat2[node * HC + tid] = v > 0.f ? v : expm1f(v);
}

// ------------- GEMM2: h2 = feat2 @ W2  (M=n, K=256, N=40) -------------------
__global__ void __launch_bounds__(256) k_gemm2(const float* __restrict__ W2, int n) {
    __shared__ float As[16][128];
    __shared__ float Bs[16][CLS];
    int t = threadIdx.x;
    int rowbase = blockIdx.x * 128;
    int ty = t >> 3, tx = t & 7;   // TM=4 rows, TN=5 cols

    float acc[4][5];
#pragma unroll
    for (int i = 0; i < 4; i++)
#pragma unroll
        for (int j = 0; j < 5; j++) acc[i][j] = 0.f;

    for (int k0 = 0; k0 < HC; k0 += 16) {
        // A tile: 128 rows x 16 k = 512 float4 -> 2 per thread
        for (int q = t; q < 512; q += 256) {
            int row = q >> 2, seg = q & 3;
            int gr = rowbase + row;
            float4 v = make_float4(0.f, 0.f, 0.f, 0.f);
            if (gr < n) v = *(const float4*)&g_feat2[gr * HC + k0 + seg * 4];
            As[seg * 4 + 0][row] = v.x;
            As[seg * 4 + 1][row] = v.y;
            As[seg * 4 + 2][row] = v.z;
            As[seg * 4 + 3][row] = v.w;
        }
        // B tile: 16 x 40 = 640 floats
        for (int q = t; q < 16 * CLS; q += 256) {
            int kk = q / CLS, c = q % CLS;
            Bs[kk][c] = W2[(k0 + kk) * CLS + c];
        }
        __syncthreads();
#pragma unroll
        for (int kk = 0; kk < 16; kk++) {
            float a[4], b[5];
#pragma unroll
            for (int i = 0; i < 4; i++) a[i] = As[kk][ty * 4 + i];
#pragma unroll
            for (int j = 0; j < 5; j++) b[j] = Bs[kk][tx * 5 + j];
#pragma unroll
            for (int i = 0; i < 4; i++)
#pragma unroll
                for (int j = 0; j < 5; j++) acc[i][j] += a[i] * b[j];
        }
        __syncthreads();
    }
#pragma unroll
    for (int i = 0; i < 4; i++) {
        int gr = rowbase + ty * 4 + i;
        if (gr < n) {
#pragma unroll
            for (int j = 0; j < 5; j++)
                g_h2[gr * CLS + tx * 5 + j] = acc[i][j];
        }
    }
}

// --------------- per-node attention dot products, layer 2 -------------------
__global__ void __launch_bounds__(64) k_alpha2(const float* __restrict__ aw_s,
                                               const float* __restrict__ aw_d, int n) {
    int node = blockIdx.x;
    int tid = threadIdx.x;
    __shared__ float rs[64], rd[64];
    float v = (tid < CLS) ? g_h2[node * CLS + tid] : 0.f;
    rs[tid] = (tid < CLS) ? v * aw_s[tid] : 0.f;
    rd[tid] = (tid < CLS) ? v * aw_d[tid] : 0.f;
    __syncthreads();
#pragma unroll
    for (int st = 32; st >= 1; st >>= 1) {
        if (tid < st) { rs[tid] += rs[tid + st]; rd[tid] += rd[tid + st]; }
        __syncthreads();
    }
    if (tid == 0) { g_as2[node] = rs[0]; g_ad2[node] = rd[0]; }
}

// ---------- fused softmax + aggregation + bias + log_softmax (layer 2) ------
__global__ void __launch_bounds__(64) k_gat2(const float* __restrict__ b2,
                                             float* __restrict__ out, int n) {
    const int CH = 64;
    int node = blockIdx.x;
    int tid = threadIdx.x;
    int base = g_rowptr[node];
    int deg = g_rowptr[node + 1] - base;

    __shared__ float red[64];
    __shared__ float sal[CH];
    __shared__ int ssrc[CH];

    float ad = g_ad2[node];

    // max
    float pm = -1e30f;
    for (int i = tid; i < deg; i += 64) {
        float e = g_as2[g_col[base + i]] + ad;
        e = e > 0.f ? e : 0.2f * e;
        pm = fmaxf(pm, e);
    }
    red[tid] = pm;
    __syncthreads();
#pragma unroll
    for (int st = 32; st >= 1; st >>= 1) {
        if (tid < st) red[tid] = fmaxf(red[tid], red[tid + st]);
        __syncthreads();
    }
    float mh = red[0];
    __syncthreads();

    // denom
    float ps = 0.f;
    for (int i = tid; i < deg; i += 64) {
        float e = g_as2[g_col[base + i]] + ad;
        e = e > 0.f ? e : 0.2f * e;
        ps += __expf(e - mh);
    }
    red[tid] = ps;
    __syncthreads();
#pragma unroll
    for (int st = 32; st >= 1; st >>= 1) {
        if (tid < st) red[tid] += red[tid + st];
        __syncthreads();
    }
    float den = red[0] + 1e-16f;
    __syncthreads();

    // aggregate
    float acc = 0.f;
    for (int cb = 0; cb < deg; cb += CH) {
        int m = min(CH, deg - cb);
        if (tid < m) {
            int s = g_col[base + cb + tid];
            ssrc[tid] = s;
            float e = g_as2[s] + ad;
            e = e > 0.f ? e : 0.2f * e;
            sal[tid] = __expf(e - mh) / den;
        }
        __syncthreads();
        if (tid < CLS) {
            for (int j = 0; j < m; j++)
                acc += sal[j] * g_h2[ssrc[j] * CLS + tid];
        }
        __syncthreads();
    }

    // bias + log_softmax over 40 classes
    float v = acc + ((tid < CLS) ? b2[tid] : 0.f);
    red[tid] = (tid < CLS) ? v : -1e30f;
    __syncthreads();
#pragma unroll
    for (int st = 32; st >= 1; st >>= 1) {
        if (tid < st) red[tid] = fmaxf(red[tid], red[tid + st]);
        __syncthreads();
    }
    float lmax = red[0];
    __syncthreads();
    red[tid] = (tid < CLS) ? __expf(v - lmax) : 0.f;
    __syncthreads();
#pragma unroll
    for (int st = 32; st >= 1; st >>= 1) {
        if (tid < st) red[tid] += red[tid + st];
        __syncthreads();
    }
    float lse = logf(red[0]);
    if (tid < CLS) out[node * CLS + tid] = v - lmax - lse;
}

// ------------------------------- launch -------------------------------------
extern "C" void kernel_launch(void* const* d_in, const int* in_sizes, int n_in,
                              void* d_out, int out_size) {
    const float* x   = (const float*)d_in[0];
    const int*   ei  = (const int*)  d_in[1];
    const float* W1  = (const float*)d_in[2];
    const float* as1 = (const float*)d_in[3];
    const float* ad1 = (const float*)d_in[4];
    const float* b1  = (const float*)d_in[5];
    const float* W2  = (const float*)d_in[6];
    const float* as2 = (const float*)d_in[7];
    const float* ad2 = (const float*)d_in[8];
    const float* b2  = (const float*)d_in[9];

    int n = in_sizes[0] / F_IN;
    int e = in_sizes[1] / 2;
    int tot = e + n;

    k_zero_deg<<<(n + 255) / 256, 256>>>(n);
    k_count<<<(tot + 255) / 256, 256>>>(ei, e, n);
    k_scan<<<1, 1024>>>(n);
    k_scatter<<<(tot + 255) / 256, 256>>>(ei, e, n);

    k_gemm1<<<dim3(HC / 128, (n + 127) / 128), 256>>>(x, W1, n);
    k_alpha1<<<(n + 7) / 8, 256>>>(as1, ad1, n);
    k_gat1<<<n, 256>>>(b1, n);

    k_gemm2<<<(n + 127) / 128, 256>>>(W2, n);
    k_alpha2<<<n, 64>>>(as2, ad2, n);
    k_gat2<<<n, 64>>>(b2, (float*)d_out, n);
}

// round 2
// speedup vs baseline: 1.4070x; 1.4070x over previous
#include <cuda_runtime.h>
#include <math.h>

#define N_MAX 50000
#define E_MAX 800000
#define F_IN  512
#define NHEAD 8
#define HC    256
#define CLS   40

// ------------------- scratch (static device globals; no allocs) -------------
__device__ float g_h1[N_MAX * HC];      // layer-1 features per head (pre-attn)
__device__ float g_feat2[N_MAX * HC];   // elu(aggregated + b1) = layer-2 input
__device__ float g_h2[N_MAX * CLS];     // layer-2 transformed features
__device__ float g_as1[N_MAX * NHEAD];
__device__ float g_ad1[N_MAX * NHEAD];
__device__ float g_as2[N_MAX];
__device__ float g_ad2[N_MAX];
__device__ int   g_deg[N_MAX];
__device__ int   g_rowptr[N_MAX + 1];
__device__ int   g_cursor[N_MAX];
__device__ int   g_col[E_MAX + N_MAX];

// ------------------------------- CSR build ---------------------------------
__global__ void k_zero_deg(int n) {
    int i = blockIdx.x * blockDim.x + threadIdx.x;
    if (i < n) g_deg[i] = 0;
}

__global__ void k_count(const int* __restrict__ ei, int e, int n) {
    int i = blockIdx.x * blockDim.x + threadIdx.x;
    int tot = e + n;
    if (i >= tot) return;
    int dst = (i < e) ? ei[e + i] : (i - e);
    atomicAdd(&g_deg[dst], 1);
}

// single-block scan: rowptr (exclusive on [0..n]) + cursor copy
__global__ void k_scan(int n) {
    __shared__ int wsum[32];
    int t = threadIdx.x, lane = t & 31, w = t >> 5;
    int carry = 0;
    for (int base = 0; base < n; base += 1024) {
        int i = base + t;
        int v = (i < n) ? g_deg[i] : 0;
        int xv = v;
#pragma unroll
        for (int off = 1; off < 32; off <<= 1) {
            int u = __shfl_up_sync(0xffffffffu, xv, off);
            if (lane >= off) xv += u;
        }
        if (lane == 31) wsum[w] = xv;
        __syncthreads();
        if (w == 0) {
            int y = wsum[lane];
#pragma unroll
            for (int off = 1; off < 32; off <<= 1) {
                int u = __shfl_up_sync(0xffffffffu, y, off);
                if (lane >= off) y += u;
            }
            wsum[lane] = y;
        }
        __syncthreads();
        int prev = (w > 0) ? wsum[w - 1] : 0;
        int incl = xv + prev;
        int tot = wsum[31];
        if (i < n) {
            g_rowptr[i + 1] = carry + incl;
            g_cursor[i] = carry + incl - v;
        }
        carry += tot;
        __syncthreads();
    }
    if (t == 0) g_rowptr[0] = 0;
}

__global__ void k_scatter(const int* __restrict__ ei, int e, int n) {
    int i = blockIdx.x * blockDim.x + threadIdx.x;
    int tot = e + n;
    if (i >= tot) return;
    int src = (i < e) ? ei[i] : (i - e);
    int dst = (i < e) ? ei[e + i] : (i - e);
    int p = atomicAdd(&g_cursor[dst], 1);
    g_col[p] = src;
}

// ------------------- GEMM1 (tf32 tensor cores) ------------------------------
// h1 = x @ W1   (M=n, K=512, N=256)
// block tile 128x128x16, 8 warps, warp tile 32x64, mma.m16n8k8.tf32

__device__ __forceinline__ unsigned f2tf32(float f) {
    unsigned r;
    asm("cvt.rna.tf32.f32 %0, %1;" : "=r"(r) : "f"(f));
    return r;
}

__device__ __forceinline__ void mma_tf32(float* c, unsigned a0, unsigned a1,
                                         unsigned a2, unsigned a3,
                                         unsigned b0, unsigned b1) {
    asm volatile(
        "mma.sync.aligned.m16n8k8.row.col.f32.tf32.tf32.f32 "
        "{%0,%1,%2,%3}, {%4,%5,%6,%7}, {%8,%9}, {%0,%1,%2,%3};"
        : "+f"(c[0]), "+f"(c[1]), "+f"(c[2]), "+f"(c[3])
        : "r"(a0), "r"(a1), "r"(a2), "r"(a3), "r"(b0), "r"(b1));
}

#define G1_BM 128
#define G1_BN 128
#define G1_BK 16

__global__ void __launch_bounds__(256) k_gemm1(const float* __restrict__ x,
                                               const float* __restrict__ W, int n) {
    __shared__ unsigned As[G1_BK][G1_BM + 8];
    __shared__ unsigned Bs[G1_BK][G1_BN + 8];
    int t = threadIdx.x;
    int warp = t >> 5, lane = t & 31;
    int g = lane >> 2, tg = lane & 3;
    int wy = warp >> 1, wx = warp & 1;           // wy: 0..3 (M), wx: 0..1 (N)
    int rowbase = blockIdx.y * G1_BM;
    int colbase = blockIdx.x * G1_BN;

    float acc[2][8][4];
#pragma unroll
    for (int mi = 0; mi < 2; mi++)
#pragma unroll
        for (int ni = 0; ni < 8; ni++)
#pragma unroll
            for (int q = 0; q < 4; q++) acc[mi][ni][q] = 0.f;

    // loader mapping
    // A: v = t + q*256 -> row = v>>2, kseg = v&3  (row-chunk of 4 k-floats)
    // B: v = t + q*256 -> krow = v>>5, cseg = v&31
    float4 aR[2], bR[2];
    {
        int k0 = 0;
#pragma unroll
        for (int q = 0; q < 2; q++) {
            int v = t + q * 256;
            int row = v >> 2, kseg = v & 3;
            int gr = rowbase + row;
            aR[q] = (gr < n) ? *(const float4*)&x[gr * F_IN + k0 + kseg * 4]
                             : make_float4(0.f, 0.f, 0.f, 0.f);
            int krow = v >> 5, cseg = v & 31;
            bR[q] = *(const float4*)&W[(k0 + krow) * HC + colbase + cseg * 4];
        }
    }

    for (int k0 = 0; k0 < F_IN; k0 += G1_BK) {
        // store staged regs to smem (as tf32 bits)
#pragma unroll
        for (int q = 0; q < 2; q++) {
            int v = t + q * 256;
            int row = v >> 2, kseg = v & 3;
            As[kseg * 4 + 0][row] = f2tf32(aR[q].x);
            As[kseg * 4 + 1][row] = f2tf32(aR[q].y);
            As[kseg * 4 + 2][row] = f2tf32(aR[q].z);
            As[kseg * 4 + 3][row] = f2tf32(aR[q].w);
            int krow = v >> 5, cseg = v & 31;
            Bs[krow][cseg * 4 + 0] = f2tf32(bR[q].x);
            Bs[krow][cseg * 4 + 1] = f2tf32(bR[q].y);
            Bs[krow][cseg * 4 + 2] = f2tf32(bR[q].z);
            Bs[krow][cseg * 4 + 3] = f2tf32(bR[q].w);
        }
        __syncthreads();

        // prefetch next tile while computing
        int kn = k0 + G1_BK;
        if (kn < F_IN) {
#pragma unroll
            for (int q = 0; q < 2; q++) {
                int v = t + q * 256;
                int row = v >> 2, kseg = v & 3;
                int gr = rowbase + row;
                aR[q] = (gr < n) ? *(const float4*)&x[gr * F_IN + kn + kseg * 4]
                                 : make_float4(0.f, 0.f, 0.f, 0.f);
                int krow = v >> 5, cseg = v & 31;
                bR[q] = *(const float4*)&W[(kn + krow) * HC + colbase + cseg * 4];
            }
        }

#pragma unroll
        for (int ks = 0; ks < G1_BK; ks += 8) {
            unsigned bf[8][2];
            int nb = wx * 64 + g;
#pragma unroll
            for (int ni = 0; ni < 8; ni++) {
                bf[ni][0] = Bs[ks + tg][nb + ni * 8];
                bf[ni][1] = Bs[ks + tg + 4][nb + ni * 8];
            }
#pragma unroll
            for (int mi = 0; mi < 2; mi++) {
                int mb = wy * 32 + mi * 16 + g;
                unsigned a0 = As[ks + tg][mb];
                unsigned a1 = As[ks + tg][mb + 8];
                unsigned a2 = As[ks + tg + 4][mb];
                unsigned a3 = As[ks + tg + 4][mb + 8];
#pragma unroll
                for (int ni = 0; ni < 8; ni++)
                    mma_tf32(acc[mi][ni], a0, a1, a2, a3, bf[ni][0], bf[ni][1]);
            }
        }
        __syncthreads();
    }

    // epilogue
#pragma unroll
    for (int mi = 0; mi < 2; mi++) {
        int r0 = rowbase + wy * 32 + mi * 16 + g;
        int r1 = r0 + 8;
#pragma unroll
        for (int ni = 0; ni < 8; ni++) {
            int c = colbase + wx * 64 + ni * 8 + tg * 2;
            if (r0 < n)
                *(float2*)&g_h1[r0 * HC + c] = make_float2(acc[mi][ni][0], acc[mi][ni][1]);
            if (r1 < n)
                *(float2*)&g_h1[r1 * HC + c] = make_float2(acc[mi][ni][2], acc[mi][ni][3]);
        }
    }
}

// --------------- per-node attention dot products, layer 1 -------------------
__global__ void k_alpha1(const float* __restrict__ aw_s,
                         const float* __restrict__ aw_d, int n) {
    int warp = (blockIdx.x * blockDim.x + threadIdx.x) >> 5;
    int lane = threadIdx.x & 31;
    if (warp >= n) return;
    const float* hrow = &g_h1[warp * HC];
    float rs[8], rd[8];
#pragma unroll
    for (int i = 0; i < 8; i++) {
        float v = hrow[i * 32 + lane];
        float s = v * aw_s[i * 32 + lane];
        float d = v * aw_d[i * 32 + lane];
#pragma unroll
        for (int off = 16; off >= 1; off >>= 1) {
            s += __shfl_xor_sync(0xffffffffu, s, off);
            d += __shfl_xor_sync(0xffffffffu, d, off);
        }
        rs[i] = s; rd[i] = d;
    }
    if (lane == 0) {
#pragma unroll
        for (int i = 0; i < 8; i++) {
            g_as1[warp * 8 + i] = rs[i];
            g_ad1[warp * 8 + i] = rd[i];
        }
    }
}

// ---------- fused segment-softmax + aggregation + bias + ELU (layer 1) ------
__global__ void __launch_bounds__(256) k_gat1(const float* __restrict__ b1, int n) {
    const int CH = 64;
    int node = blockIdx.x;
    int tid = threadIdx.x;
    int base = g_rowptr[node];
    int deg = g_rowptr[node + 1] - base;

    __shared__ float red[256];
    __shared__ float hmax[8], hden[8], adl[8];
    __shared__ float sal[CH * 8];
    __shared__ int ssrc[CH];

    if (tid < 8) adl[tid] = g_ad1[node * 8 + tid];
    __syncthreads();
    int hh = tid & 7;
    float ad = adl[hh];

    // pass A: per-head max
    float pm = -1e30f;
    for (int i = tid; i < deg * 8; i += 256) {
        int j = i >> 3;
        int s = g_col[base + j];
        float e = g_as1[s * 8 + hh] + ad;
        e = e > 0.f ? e : 0.2f * e;
        pm = fmaxf(pm, e);
    }
    red[tid] = pm;
    __syncthreads();
#pragma unroll
    for (int st = 128; st >= 8; st >>= 1) {
        if (tid < st) red[tid] = fmaxf(red[tid], red[tid + st]);
        __syncthreads();
    }
    if (tid < 8) hmax[tid] = red[tid];
    __syncthreads();
    float mh = hmax[hh];

    // pass B: per-head denominator
    float ps = 0.f;
    for (int i = tid; i < deg * 8; i += 256) {
        int j = i >> 3;
        int s = g_col[base + j];
        float e = g_as1[s * 8 + hh] + ad;
        e = e > 0.f ? e : 0.2f * e;
        ps += __expf(e - mh);
    }
    red[tid] = ps;
    __syncthreads();
#pragma unroll
    for (int st = 128; st >= 8; st >>= 1) {
        if (tid < st) red[tid] += red[tid + st];
        __syncthreads();
    }
    if (tid < 8) hden[tid] = red[tid] + 1e-16f;
    __syncthreads();
    float dh = hden[hh];

    // pass C: aggregate; thread tid owns slot (h = tid/32, c = tid%32)
    float acc = 0.f;
    int myh = tid >> 5;
    for (int cb = 0; cb < deg; cb += CH) {
        int m = min(CH, deg - cb);
        __syncthreads();
        if (tid < m) ssrc[tid] = g_col[base + cb + tid];
        __syncthreads();
        for (int i = tid; i < m * 8; i += 256) {
            int j = i >> 3;
            float e = g_as1[ssrc[j] * 8 + hh] + ad;
            e = e > 0.f ? e : 0.2f * e;
            sal[i] = __expf(e - mh) / dh;
        }
        __syncthreads();
        for (int j = 0; j < m; j++) {
            acc += sal[j * 8 + myh] * g_h1[ssrc[j] * HC + tid];
        }
    }
    float v = acc + b1[tid];
    g_feat2[node * HC + tid] = v > 0.f ? v : expm1f(v);
}

// ------------- GEMM2: h2 = feat2 @ W2  (M=n, K=256, N=40) -------------------
__global__ void __launch_bounds__(256) k_gemm2(const float* __restrict__ W2, int n) {
    __shared__ float As[16][128];
    __shared__ float Bs[16][CLS];
    int t = threadIdx.x;
    int rowbase = blockIdx.x * 128;
    int ty = t >> 3, tx = t & 7;   // TM=4 rows, TN=5 cols

    float acc[4][5];
#pragma unroll
    for (int i = 0; i < 4; i++)
#pragma unroll
        for (int j = 0; j < 5; j++) acc[i][j] = 0.f;

    for (int k0 = 0; k0 < HC; k0 += 16) {
        for (int q = t; q < 512; q += 256) {
            int row = q >> 2, seg = q & 3;
            int gr = rowbase + row;
            float4 v = make_float4(0.f, 0.f, 0.f, 0.f);
            if (gr < n) v = *(const float4*)&g_feat2[gr * HC + k0 + seg * 4];
            As[seg * 4 + 0][row] = v.x;
            As[seg * 4 + 1][row] = v.y;
            As[seg * 4 + 2][row] = v.z;
            As[seg * 4 + 3][row] = v.w;
        }
        for (int q = t; q < 16 * CLS; q += 256) {
            int kk = q / CLS, c = q % CLS;
            Bs[kk][c] = W2[(k0 + kk) * CLS + c];
        }
        __syncthreads();
#pragma unroll
        for (int kk = 0; kk < 16; kk++) {
            float a[4], b[5];
#pragma unroll
            for (int i = 0; i < 4; i++) a[i] = As[kk][ty * 4 + i];
#pragma unroll
            for (int j = 0; j < 5; j++) b[j] = Bs[kk][tx * 5 + j];
#pragma unroll
            for (int i = 0; i < 4; i++)
#pragma unroll
                for (int j = 0; j < 5; j++) acc[i][j] += a[i] * b[j];
        }
        __syncthreads();
    }
#pragma unroll
    for (int i = 0; i < 4; i++) {
        int gr = rowbase + ty * 4 + i;
        if (gr < n) {
#pragma unroll
            for (int j = 0; j < 5; j++)
                g_h2[gr * CLS + tx * 5 + j] = acc[i][j];
        }
    }
}

// --------------- per-node attention dot products, layer 2 -------------------
__global__ void __launch_bounds__(64) k_alpha2(const float* __restrict__ aw_s,
                                               const float* __restrict__ aw_d, int n) {
    int node = blockIdx.x;
    int tid = threadIdx.x;
    __shared__ float rs[64], rd[64];
    float v = (tid < CLS) ? g_h2[node * CLS + tid] : 0.f;
    rs[tid] = (tid < CLS) ? v * aw_s[tid] : 0.f;
    rd[tid] = (tid < CLS) ? v * aw_d[tid] : 0.f;
    __syncthreads();
#pragma unroll
    for (int st = 32; st >= 1; st >>= 1) {
        if (tid < st) { rs[tid] += rs[tid + st]; rd[tid] += rd[tid + st]; }
        __syncthreads();
    }
    if (tid == 0) { g_as2[node] = rs[0]; g_ad2[node] = rd[0]; }
}

// ---------- fused softmax + aggregation + bias + log_softmax (layer 2) ------
__global__ void __launch_bounds__(64) k_gat2(const float* __restrict__ b2,
                                             float* __restrict__ out, int n) {
    const int CH = 64;
    int node = blockIdx.x;
    int tid = threadIdx.x;
    int base = g_rowptr[node];
    int deg = g_rowptr[node + 1] - base;

    __shared__ float red[64];
    __shared__ float sal[CH];
    __shared__ int ssrc[CH];

    float ad = g_ad2[node];

    float pm = -1e30f;
    for (int i = tid; i < deg; i += 64) {
        float e = g_as2[g_col[base + i]] + ad;
        e = e > 0.f ? e : 0.2f * e;
        pm = fmaxf(pm, e);
    }
    red[tid] = pm;
    __syncthreads();
#pragma unroll
    for (int st = 32; st >= 1; st >>= 1) {
        if (tid < st) red[tid] = fmaxf(red[tid], red[tid + st]);
        __syncthreads();
    }
    float mh = red[0];
    __syncthreads();

    float ps = 0.f;
    for (int i = tid; i < deg; i += 64) {
        float e = g_as2[g_col[base + i]] + ad;
        e = e > 0.f ? e : 0.2f * e;
        ps += __expf(e - mh);
    }
    red[tid] = ps;
    __syncthreads();
#pragma unroll
    for (int st = 32; st >= 1; st >>= 1) {
        if (tid < st) red[tid] += red[tid + st];
        __syncthreads();
    }
    float den = red[0] + 1e-16f;
    __syncthreads();

    float acc = 0.f;
    for (int cb = 0; cb < deg; cb += CH) {
        int m = min(CH, deg - cb);
        if (tid < m) {
            int s = g_col[base + cb + tid];
            ssrc[tid] = s;
            float e = g_as2[s] + ad;
            e = e > 0.f ? e : 0.2f * e;
            sal[tid] = __expf(e - mh) / den;
        }
        __syncthreads();
        if (tid < CLS) {
            for (int j = 0; j < m; j++)
                acc += sal[j] * g_h2[ssrc[j] * CLS + tid];
        }
        __syncthreads();
    }

    float v = acc + ((tid < CLS) ? b2[tid] : 0.f);
    red[tid] = (tid < CLS) ? v : -1e30f;
    __syncthreads();
#pragma unroll
    for (int st = 32; st >= 1; st >>= 1) {
        if (tid < st) red[tid] = fmaxf(red[tid], red[tid + st]);
        __syncthreads();
    }
    float lmax = red[0];
    __syncthreads();
    red[tid] = (tid < CLS) ? __expf(v - lmax) : 0.f;
    __syncthreads();
#pragma unroll
    for (int st = 32; st >= 1; st >>= 1) {
        if (tid < st) red[tid] += red[tid + st];
        __syncthreads();
    }
    float lse = logf(red[0]);
    if (tid < CLS) out[node * CLS + tid] = v - lmax - lse;
}

// ------------------------------- launch -------------------------------------
extern "C" void kernel_launch(void* const* d_in, const int* in_sizes, int n_in,
                              void* d_out, int out_size) {
    const float* x   = (const float*)d_in[0];
    const int*   ei  = (const int*)  d_in[1];
    const float* W1  = (const float*)d_in[2];
    const float* as1 = (const float*)d_in[3];
    const float* ad1 = (const float*)d_in[4];
    const float* b1  = (const float*)d_in[5];
    const float* W2  = (const float*)d_in[6];
    const float* as2 = (const float*)d_in[7];
    const float* ad2 = (const float*)d_in[8];
    const float* b2  = (const float*)d_in[9];

    int n = in_sizes[0] / F_IN;
    int e = in_sizes[1] / 2;
    int tot = e + n;

    k_zero_deg<<<(n + 255) / 256, 256>>>(n);
    k_count<<<(tot + 255) / 256, 256>>>(ei, e, n);
    k_scan<<<1, 1024>>>(n);
    k_scatter<<<(tot + 255) / 256, 256>>>(ei, e, n);

    k_gemm1<<<dim3(HC / G1_BN, (n + G1_BM - 1) / G1_BM), 256>>>(x, W1, n);
    k_alpha1<<<(n + 7) / 8, 256>>>(as1, ad1, n);
    k_gat1<<<n, 256>>>(b1, n);

    k_gemm2<<<(n + 127) / 128, 256>>>(W2, n);
    k_alpha2<<<n, 64>>>(as2, ad2, n);
    k_gat2<<<n, 64>>>(b2, (float*)d_out, n);
}